// round 16
// baseline (speedup 1.0000x reference)
#include <cuda_runtime.h>
#include <math.h>

#define NB 2
#define L 196
#define D 768
#define LD (L*D)
#define MW 7
#define NLTOT (NB*L)   // 392
#define STRH 448
#define SPK 7

// ---------------- scratch ---------------------------------------------------
__device__ float    g_V   [NB*LD];
__device__ float    g_Xr  [NLTOT*STRH];
__device__ float    g_Xi  [NLTOT*STRH];
__device__ float    g_sty [NLTOT*STRH];
__device__ float    g_Sn  [SPK][NLTOT*STRH];
__device__ float    g_Sd  [SPK][NLTOT*STRH];
__device__ float    g_B1  [NLTOT*STRH];
__device__ float    g_B2  [NLTOT*STRH];
__device__ float    g_B3  [NLTOT*STRH];
__device__ float    g_rsum[NLTOT];
__device__ unsigned g_M   [NB*L*MW];
__device__ int      g_nzero;

// ---------------- f32x2 helpers ---------------------------------------------
typedef unsigned long long u64;
__device__ __forceinline__ void fma2(u64 &acc, u64 a, u64 b) {
    asm("fma.rn.f32x2 %0, %1, %2, %0;" : "+l"(acc) : "l"(a), "l"(b));
}
__device__ __forceinline__ u64 pack2(float x, float y) {
    u64 r; asm("mov.b64 %0, {%1, %2};" : "=l"(r) : "f"(x), "f"(y)); return r;
}
__device__ __forceinline__ float2 unpack2(u64 v) {
    float2 f; asm("mov.b64 {%0, %1}, %2;" : "=f"(f.x), "=f"(f.y) : "l"(v)); return f;
}

__device__ __forceinline__ float2 blockSum256x2(float2 v, float2* red) {
    #pragma unroll
    for (int o = 16; o; o >>= 1) {
        v.x += __shfl_xor_sync(0xffffffffu, v.x, o);
        v.y += __shfl_xor_sync(0xffffffffu, v.y, o);
    }
    if ((threadIdx.x & 31) == 0) red[threadIdx.x >> 5] = v;
    __syncthreads();
    if (threadIdx.x < 32) {
        float2 x = (threadIdx.x < 8) ? red[threadIdx.x] : make_float2(0.f, 0.f);
        #pragma unroll
        for (int o = 4; o; o >>= 1) {
            x.x += __shfl_xor_sync(0xffffffffu, x.x, o);
            x.y += __shfl_xor_sync(0xffffffffu, x.y, o);
        }
        if (threadIdx.x == 0) red[0] = x;
    }
    __syncthreads();
    float2 r = red[0];
    __syncthreads();
    return r;
}

__device__ __forceinline__ void build_tw(float2* tw, int tid) {
    if (tid < 192) {
        float s, c; sincospif((float)tid * (1.f / 384.f), &s, &c);
        tw[tid]       = make_float2(c, s);
        tw[tid + 192] = make_float2(-s, c);
        tw[tid + 384] = make_float2(-c, -s);
    }
}

// ---------------- Stockham FFT N=768 = 3*4^4 ---------------------------------
__device__ __forceinline__ float2* fft768r4(float2* a, float2* b,
                                            const float2* tw, int tid, float sgn) {
    {
        const float c3 = 0.8660254037844386f * sgn;
        float2 x0 = a[tid], x1 = a[tid + 256], x2 = a[tid + 512];
        float2 s = make_float2(x1.x + x2.x, x1.y + x2.y);
        float2 d = make_float2(x1.x - x2.x, x1.y - x2.y);
        float mr = x0.x - 0.5f * s.x, mi = x0.y - 0.5f * s.y;
        b[3 * tid]     = make_float2(x0.x + s.x, x0.y + s.y);
        b[3 * tid + 1] = make_float2(mr - c3 * d.y, mi + c3 * d.x);
        b[3 * tid + 2] = make_float2(mr + c3 * d.y, mi - c3 * d.x);
    }
    __syncthreads();
    float2* src = b; float2* dst = a;
    #pragma unroll
    for (int st = 0; st < 4; st++) {
        const int l = 3 << (2 * st);
        const int step = 64 >> (2 * st);
        if (tid < 192) {
            int j = tid;
            int k = j % l;
            int idx = k * step;
            float2 v0 = src[j], v1 = src[j + 192], v2 = src[j + 384], v3 = src[j + 576];
            float2 w1 = tw[idx], w2 = tw[2 * idx], w3 = tw[3 * idx];
            float s1 = sgn * w1.y, s2 = sgn * w2.y, s3 = sgn * w3.y;
            float2 t1 = make_float2(v1.x * w1.x - v1.y * s1, v1.x * s1 + v1.y * w1.x);
            float2 t2 = make_float2(v2.x * w2.x - v2.y * s2, v2.x * s2 + v2.y * w2.x);
            float2 t3 = make_float2(v3.x * w3.x - v3.y * s3, v3.x * s3 + v3.y * w3.x);
            float2 e0 = make_float2(v0.x + t2.x, v0.y + t2.y);
            float2 e1 = make_float2(v0.x - t2.x, v0.y - t2.y);
            float2 o0 = make_float2(t1.x + t3.x, t1.y + t3.y);
            float2 o1 = make_float2(t1.x - t3.x, t1.y - t3.y);
            float2 io = make_float2(-sgn * o1.y, sgn * o1.x);
            int ob = 4 * j - 3 * k;
            dst[ob]         = make_float2(e0.x + o0.x, e0.y + o0.y);
            dst[ob + l]     = make_float2(e1.x + io.x, e1.y + io.y);
            dst[ob + 2 * l] = make_float2(e0.x - o0.x, e0.y - o0.y);
            dst[ob + 3 * l] = make_float2(e1.x - io.x, e1.y - io.y);
        }
        __syncthreads();
        float2* t = src; src = dst; dst = t;
    }
    return src;
}

// ============ Kernel A1: paired patch(196) | rowsum(49) | misc(11) ===========
#define A1_PATCH 196
#define A1_RS    49
#define A1_MISC  11
#define A1_GRID  (A1_PATCH + A1_RS + A1_MISC)

__global__ void k_A1(const float* __restrict__ imgs, const float* __restrict__ x,
                     float* __restrict__ out, const float* __restrict__ ls) {
    __shared__ float2 red[8];
    __shared__ float buf[2 * D];
    int b = blockIdx.x, tid = threadIdx.x;
    if (b < A1_PATCH) {
        int p = tid >> 4, q = tid & 15;
        const float* base[2];
        #pragma unroll
        for (int rr = 0; rr < 2; rr++) {
            int blk = 2 * b + rr, a = blk / L, l = blk % L;
            int hh = l / 14, ww = l % 14;
            base[rr] = imgs + ((size_t)a * 3 * 224 + (size_t)(hh * 16 + p)) * 224
                            + (ww * 16 + q);
        }
        float v0[3], v1[3];
        #pragma unroll
        for (int c = 0; c < 3; c++) {
            v0[c] = base[0][(size_t)c * 224 * 224];
            v1[c] = base[1][(size_t)c * 224 * 224];
        }
        float2 sums = blockSum256x2(
            make_float2(v0[0] + v0[1] + v0[2], v1[0] + v1[1] + v1[2]), red);
        float mean0 = sums.x * (1.f / 768.f), mean1 = sums.y * (1.f / 768.f);
        float u0[3], u1[3]; float ss0 = 0.f, ss1 = 0.f;
        #pragma unroll
        for (int c = 0; c < 3; c++) {
            u0[c] = v0[c] - mean0; ss0 += u0[c] * u0[c];
            u1[c] = v1[c] - mean1; ss1 += u1[c] * u1[c];
        }
        float2 tot = blockSum256x2(make_float2(ss0, ss1), red);
        float inv0 = 1.f / sqrtf(tot.x);
        float inv1 = 1.f / sqrtf(tot.y);
        #pragma unroll
        for (int c = 0; c < 3; c++) {
            buf[tid * 3 + c]     = u0[c] * inv0;
            buf[D + tid * 3 + c] = u1[c] * inv1;
        }
        __syncthreads();
        if (tid < 192) {
            reinterpret_cast<float4*>(g_V + (size_t)(2 * b) * D)[tid] =
                reinterpret_cast<float4*>(buf)[tid];
            reinterpret_cast<float4*>(g_V + (size_t)(2 * b + 1) * D)[tid] =
                reinterpret_cast<float4*>(buf + D)[tid];
        }
        return;
    }
    b -= A1_PATCH;
    if (b < A1_RS) {
        int w = tid >> 5, lane = tid & 31;
        int row = b * 8 + w;
        if (row < NLTOT) {
            int a = row / L, i = row % L;
            const float* lp = ls + ((size_t)a * L + i) * L;
            float s = 0.f;
            for (int j = lane; j < L; j += 32) s += lp[j];
            #pragma unroll
            for (int o = 16; o; o >>= 1) s += __shfl_xor_sync(0xffffffffu, s, o);
            if (lane == 0) g_rsum[row] = s;
        }
        return;
    }
    b -= A1_RS;
    {
        int t = b * 256 + tid;
        if (t < NB * L * MW) g_M[t] = 0u;
        if (t < NB * D) {
            int a = t / D, d = t % D;
            out[(size_t)a * 197 * D + d] = x[(size_t)a * 197 * D + d];
        }
        if (t == 0) g_nzero = 0;
    }
}

// ============ Kernel A2: paired fwd FFT(196) | sim(56) — one wave ============
__global__ void k_A2(const float* __restrict__ x) {
    __shared__ __align__(16) float S[4400];
    int b = blockIdx.x, tid = threadIdx.x;
    if (b < NLTOT / 2) {
        float2* fa = (float2*)S;
        float2* fb = fa + 768;
        float2* tw = fa + 1536;
        build_tw(tw, tid);
        int r0 = 2 * b, r1 = 2 * b + 1;
        int a0 = r0 / L, i0 = r0 % L;
        int a1 = r1 / L, i1 = r1 % L;
        const float* xp0 = x + ((size_t)(a0 * 197 + 1 + i0)) * D;
        const float* xp1 = x + ((size_t)(a1 * 197 + 1 + i1)) * D;
        for (int d = tid; d < D; d += 256)
            fa[d] = make_float2(xp0[d], xp1[d]);
        __syncthreads();
        float2* res = fft768r4(fa, fb, tw, tid, -1.0f);
        size_t b0 = (size_t)r0 * STRH, b1 = (size_t)r1 * STRH;
        for (int k = tid; k <= 384; k += 256) {
            float2 Zk = res[k];
            float2 Zn = res[(768 - k) % 768];
            float x0r = 0.5f * (Zk.x + Zn.x), x0i = 0.5f * (Zk.y - Zn.y);
            float x1r = 0.5f * (Zk.y + Zn.y), x1i = 0.5f * (Zn.x - Zk.x);
            g_Xr[b0 + k] = x0r; g_Xi[b0 + k] = x0i;
            g_sty[b0 + k] = sqrtf(x0r * x0r + x0i * x0i);
            g_Xr[b1 + k] = x1r; g_Xi[b1 + k] = x1i;
            g_sty[b1 + k] = sqrtf(x1r * x1r + x1i * x1i);
        }
        return;
    }
    {
        // ---- sim: 32x32 upper-tri tile, double-buffered ----
        int bb = b - NLTOT / 2;
        int a = bb / 28;
        int t = bb % 28, bi = 0;
        while (t >= 7 - bi) { t -= 7 - bi; bi++; }
        int bj = bi + t;
        int i0 = bi * 32, j0 = bj * 32;
        float (*As)[34] = (float(*)[34])S;
        float (*Bs)[34] = (float(*)[34])(S + 2176);
        int tx = tid & 15, ty = tid >> 4;
        int m = tid >> 3, k4 = (tid & 7) << 2;
        const float* Vb = g_V + (size_t)a * LD;
        const float* Arow = (i0 + m < L) ? Vb + (size_t)(i0 + m) * D : nullptr;
        const float* Brow = (j0 + m < L) ? Vb + (size_t)(j0 + m) * D : nullptr;
        float4 z4 = make_float4(0.f, 0.f, 0.f, 0.f);
        float4 avP = Arow ? *reinterpret_cast<const float4*>(Arow + k4) : z4;
        float4 bvP = Brow ? *reinterpret_cast<const float4*>(Brow + k4) : z4;
        u64 acc[2] = {0ULL, 0ULL};
        int p = 0;
        As[k4 + 0][m] = avP.x; As[k4 + 1][m] = avP.y;
        As[k4 + 2][m] = avP.z; As[k4 + 3][m] = avP.w;
        Bs[k4 + 0][m] = bvP.x; Bs[k4 + 1][m] = bvP.y;
        Bs[k4 + 2][m] = bvP.z; Bs[k4 + 3][m] = bvP.w;
        __syncthreads();
        for (int k0 = 0; k0 < D; k0 += 32) {
            int kn = k0 + 32;
            if (kn < D) {
                avP = Arow ? *reinterpret_cast<const float4*>(Arow + kn + k4) : z4;
                bvP = Brow ? *reinterpret_cast<const float4*>(Brow + kn + k4) : z4;
            }
            int pb = p * 32;
            #pragma unroll
            for (int kk = 0; kk < 32; kk++) {
                float2 a2 = *reinterpret_cast<float2*>(&As[pb + kk][ty << 1]);
                u64 bbv = *reinterpret_cast<u64*>(&Bs[pb + kk][tx << 1]);
                fma2(acc[0], pack2(a2.x, a2.x), bbv);
                fma2(acc[1], pack2(a2.y, a2.y), bbv);
            }
            if (kn < D) {
                int qb = (1 - p) * 32;
                As[qb + k4 + 0][m] = avP.x; As[qb + k4 + 1][m] = avP.y;
                As[qb + k4 + 2][m] = avP.z; As[qb + k4 + 3][m] = avP.w;
                Bs[qb + k4 + 0][m] = bvP.x; Bs[qb + k4 + 1][m] = bvP.y;
                Bs[qb + k4 + 2][m] = bvP.z; Bs[qb + k4 + 3][m] = bvP.w;
                __syncthreads();
                p ^= 1;
            }
        }
        #pragma unroll
        for (int r = 0; r < 2; r++) {
            int i = i0 + (ty << 1) + r;
            if (i >= L) continue;
            float2 c = unpack2(acc[r]);
            int j = j0 + (tx << 1);
            if (j < L && j >= i && c.x > 0.3f)
                atomicOr(&g_M[(a * L + i) * MW + (j >> 5)], 1u << (j & 31));
            j++;
            if (j < L && j >= i && c.y > 0.3f)
                atomicOr(&g_M[(a * L + i) * MW + (j >> 5)], 1u << (j & 31));
        }
    }
}

// ============ Kernel C: per-row prop replay + stats + nzero ==================
__global__ void k_C() {
    __shared__ unsigned m[NB * L * MW];
    __shared__ int sS, sRem, ired[8];
    int blk = blockIdx.x, a = blk / L, i = blk % L;
    int tid = threadIdx.x;
    int local = 0;
    for (int t = tid; t < NB * L * MW; t += 256) {
        unsigned w = g_M[t]; m[t] = w; local += __popc(w);
    }
    #pragma unroll
    for (int o = 16; o; o >>= 1) local += __shfl_xor_sync(0xffffffffu, local, o);
    if ((tid & 31) == 0) ired[tid >> 5] = local;
    __syncthreads();
    if (tid == 0) {
        int s = 0;
        #pragma unroll
        for (int w = 0; w < 8; w++) s += ired[w];
        sS = s;
    }
    __syncthreads();
    for (int ii = 0; ii < i; ii++) {
        if (sS == NB * L) break;
        if (tid == 0) sRem = 0;
        __syncthreads();
        int rem = 0;
        int nj = L - 1 - ii;
        int cnt = NB * nj * MW;
        for (int t = tid; t < cnt; t += 256) {
            int w = t % MW; int r = t / MW;
            int j = ii + 1 + (r % nj); int aa = r / nj;
            unsigned rw  = m[(aa * L + ii) * MW + w];
            unsigned old = m[(aa * L + j) * MW + w];
            unsigned drop = old & rw;
            if (drop) { m[(aa * L + j) * MW + w] = old & ~rw; rem += __popc(drop); }
        }
        #pragma unroll
        for (int o = 16; o; o >>= 1) rem += __shfl_xor_sync(0xffffffffu, rem, o);
        if ((tid & 31) == 0 && rem) atomicAdd(&sRem, rem);
        __syncthreads();
        if (tid == 0) sS -= sRem;
        __syncthreads();
    }
    const unsigned* mw = &m[(a * L + i) * MW];
    int num = 0;
    #pragma unroll
    for (int w = 0; w < MW; w++) num += __popc(mw[w]);
    float numc = (num > 0) ? (float)num : 1e-7f;
    bool has2 = tid < 129;
    int c1 = tid, c2 = tid + 256;
    float S1a = 0.f, S1b = 0.f;
    for (int w = 0; w < MW; w++) {
        unsigned bits = mw[w];
        while (bits) {
            int j = (w << 5) + __ffs((int)bits) - 1; bits &= bits - 1;
            const float* sp = g_sty + (size_t)(a * L + j) * STRH;
            S1a += sp[c1];
            if (has2) S1b += sp[c2];
        }
    }
    float avga = S1a / numc, avgb = S1b / numc;
    float S2a = 0.f, S2b = 0.f;
    for (int w = 0; w < MW; w++) {
        unsigned bits = mw[w];
        while (bits) {
            int j = (w << 5) + __ffs((int)bits) - 1; bits &= bits - 1;
            const float* sp = g_sty + (size_t)(a * L + j) * STRH;
            float xa = sp[c1] - avga; S2a += xa * xa;
            if (has2) { float xb = sp[c2] - avgb; S2b += xb * xb; }
        }
    }
    size_t off = (size_t)blk * STRH;
    float sta = sqrtf(S2a / numc);
    float ma = (S1a > 0.f) ? 1.f : 0.f;
    if (!(S1a > 0.f)) atomicAdd(&g_nzero, 1);
    g_B1[off + c1] = ma * sta; g_B2[off + c1] = ma * avga; g_B3[off + c1] = ma;
    if (has2) {
        float stb = sqrtf(S2b / numc);
        float mb = (S1b > 0.f) ? 1.f : 0.f;
        if (!(S1b > 0.f)) atomicAdd(&g_nzero, 1);
        g_B1[off + c2] = mb * stb; g_B2[off + c2] = mb * avgb; g_B3[off + c2] = mb;
    } else if (tid < 192) {
        g_B1[off + c2] = 0.f; g_B2[off + c2] = 0.f; g_B3[off + c2] = 0.f;
    }
}

// ============ Kernel D: split-K(7) GEMM; cols 0..383; dead-warp skip =========
#define ARS 68
__global__ void __launch_bounds__(256, 3)
k_D(const float* __restrict__ ls, const float* __restrict__ noise) {
    __shared__ __align__(16) float SD[5 * 32 * ARS];
    __shared__ int s_nz;
    float* A1s = SD;
    float* A2s = SD + 32 * ARS;
    float* B1s = SD + 64 * ARS;
    float* B2s = SD + 96 * ARS;
    float* B3s = SD + 128 * ARS;
    int tid = threadIdx.x;
    if (tid == 0) s_nz = g_nzero;
    int tx = tid & 15, ty = tid >> 4;
    int n0 = blockIdx.x * 64, m0 = blockIdx.y * 64;
    int a = blockIdx.z / SPK, q = blockIdx.z % SPK;
    int kbeg = (q == 0) ? 0 : 16 + 32 * (q - 1);
    int kend = 16 + 32 * q;
    bool rowAct = (m0 + (ty << 2)) < L;     // any of this thread's 4 rows valid
    u64 acn[4][2], acd[4][2];
    #pragma unroll
    for (int i = 0; i < 4; i++) {
        acn[i][0] = acn[i][1] = 0ULL;
        acd[i][0] = acd[i][1] = 0ULL;
    }
    int lm = tid >> 2, lk = (tid & 3) << 2;
    int bk = tid >> 4, bn4 = (tid & 15) << 2;
    const float* lsb = ls    + (size_t)a * L * L;
    const float* nsb = noise + (size_t)a * L * L;
    float4 z4 = make_float4(0.f, 0.f, 0.f, 0.f);
    int ia = m0 + lm;
    bool iav = ia < L;
    float4 lvP = z4, nvP = z4;
    {
        int ja = kbeg + lk;
        if (iav && ja < L) {
            lvP = *reinterpret_cast<const float4*>(lsb + (size_t)ia * L + ja);
            nvP = *reinterpret_cast<const float4*>(nsb + (size_t)ia * L + ja);
        }
    }
    float4 b1P = z4, b2P = z4, b3P = z4;
    __syncthreads();
    bool fast = (s_nz == 0);
    {
        int jb = kbeg + bk;
        if (jb < L) {
            size_t o = (size_t)(a * L + jb) * STRH + n0 + bn4;
            b1P = *reinterpret_cast<const float4*>(&g_B1[o]);
            b2P = *reinterpret_cast<const float4*>(&g_B2[o]);
            if (!fast) b3P = *reinterpret_cast<const float4*>(&g_B3[o]);
        }
    }
    int p = 0;
    {
        const float* lv = reinterpret_cast<const float*>(&lvP);
        const float* nv = reinterpret_cast<const float*>(&nvP);
        #pragma unroll
        for (int t = 0; t < 4; t++) {
            A1s[(lk + t) * ARS + lm] = lv[t] * nv[t];
            A2s[(lk + t) * ARS + lm] = lv[t];
        }
        *reinterpret_cast<float4*>(&B1s[bk * ARS + bn4]) = b1P;
        *reinterpret_cast<float4*>(&B2s[bk * ARS + bn4]) = b2P;
        if (!fast) *reinterpret_cast<float4*>(&B3s[bk * ARS + bn4]) = b3P;
    }
    __syncthreads();
    for (int k0 = kbeg; k0 < kend; k0 += 16) {
        int kn = k0 + 16;
        if (kn < kend) {
            lvP = z4; nvP = z4;
            int ja = kn + lk;
            if (iav && ja < L) {
                lvP = *reinterpret_cast<const float4*>(lsb + (size_t)ia * L + ja);
                nvP = *reinterpret_cast<const float4*>(nsb + (size_t)ia * L + ja);
            }
            int jb = kn + bk;
            b1P = z4; b2P = z4; b3P = z4;
            if (jb < L) {
                size_t o = (size_t)(a * L + jb) * STRH + n0 + bn4;
                b1P = *reinterpret_cast<const float4*>(&g_B1[o]);
                b2P = *reinterpret_cast<const float4*>(&g_B2[o]);
                if (!fast) b3P = *reinterpret_cast<const float4*>(&g_B3[o]);
            }
        }
        int pb = p * 16;
        if (rowAct) {
            if (fast) {
                #pragma unroll
                for (int kk = 0; kk < 16; kk++) {
                    float4 a1 = *reinterpret_cast<float4*>(&A1s[(pb + kk) * ARS + (ty << 2)]);
                    float4 a2 = *reinterpret_cast<float4*>(&A2s[(pb + kk) * ARS + (ty << 2)]);
                    ulonglong2 b1 = *reinterpret_cast<ulonglong2*>(&B1s[(pb + kk) * ARS + (tx << 2)]);
                    ulonglong2 b2 = *reinterpret_cast<ulonglong2*>(&B2s[(pb + kk) * ARS + (tx << 2)]);
                    u64 aa;
                    aa = pack2(a1.x, a1.x); fma2(acn[0][0], aa, b1.x); fma2(acn[0][1], aa, b1.y);
                    aa = pack2(a2.x, a2.x); fma2(acn[0][0], aa, b2.x); fma2(acn[0][1], aa, b2.y);
                    aa = pack2(a1.y, a1.y); fma2(acn[1][0], aa, b1.x); fma2(acn[1][1], aa, b1.y);
                    aa = pack2(a2.y, a2.y); fma2(acn[1][0], aa, b2.x); fma2(acn[1][1], aa, b2.y);
                    aa = pack2(a1.z, a1.z); fma2(acn[2][0], aa, b1.x); fma2(acn[2][1], aa, b1.y);
                    aa = pack2(a2.z, a2.z); fma2(acn[2][0], aa, b2.x); fma2(acn[2][1], aa, b2.y);
                    aa = pack2(a1.w, a1.w); fma2(acn[3][0], aa, b1.x); fma2(acn[3][1], aa, b1.y);
                    aa = pack2(a2.w, a2.w); fma2(acn[3][0], aa, b2.x); fma2(acn[3][1], aa, b2.y);
                }
            } else {
                #pragma unroll
                for (int kk = 0; kk < 16; kk++) {
                    float4 a1 = *reinterpret_cast<float4*>(&A1s[(pb + kk) * ARS + (ty << 2)]);
                    float4 a2 = *reinterpret_cast<float4*>(&A2s[(pb + kk) * ARS + (ty << 2)]);
                    ulonglong2 b1 = *reinterpret_cast<ulonglong2*>(&B1s[(pb + kk) * ARS + (tx << 2)]);
                    ulonglong2 b2 = *reinterpret_cast<ulonglong2*>(&B2s[(pb + kk) * ARS + (tx << 2)]);
                    ulonglong2 b3 = *reinterpret_cast<ulonglong2*>(&B3s[(pb + kk) * ARS + (tx << 2)]);
                    u64 aa;
                    aa = pack2(a1.x, a1.x); fma2(acn[0][0], aa, b1.x); fma2(acn[0][1], aa, b1.y);
                    aa = pack2(a2.x, a2.x); fma2(acn[0][0], aa, b2.x); fma2(acn[0][1], aa, b2.y);
                                            fma2(acd[0][0], aa, b3.x); fma2(acd[0][1], aa, b3.y);
                    aa = pack2(a1.y, a1.y); fma2(acn[1][0], aa, b1.x); fma2(acn[1][1], aa, b1.y);
                    aa = pack2(a2.y, a2.y); fma2(acn[1][0], aa, b2.x); fma2(acn[1][1], aa, b2.y);
                                            fma2(acd[1][0], aa, b3.x); fma2(acd[1][1], aa, b3.y);
                    aa = pack2(a1.z, a1.z); fma2(acn[2][0], aa, b1.x); fma2(acn[2][1], aa, b1.y);
                    aa = pack2(a2.z, a2.z); fma2(acn[2][0], aa, b2.x); fma2(acn[2][1], aa, b2.y);
                                            fma2(acd[2][0], aa, b3.x); fma2(acd[2][1], aa, b3.y);
                    aa = pack2(a1.w, a1.w); fma2(acn[3][0], aa, b1.x); fma2(acn[3][1], aa, b1.y);
                    aa = pack2(a2.w, a2.w); fma2(acn[3][0], aa, b2.x); fma2(acn[3][1], aa, b2.y);
                                            fma2(acd[3][0], aa, b3.x); fma2(acd[3][1], aa, b3.y);
                }
            }
        }
        if (kn < kend) {
            int qb = (1 - p) * 16;
            const float* lv = reinterpret_cast<const float*>(&lvP);
            const float* nv = reinterpret_cast<const float*>(&nvP);
            #pragma unroll
            for (int t = 0; t < 4; t++) {
                A1s[(qb + lk + t) * ARS + lm] = lv[t] * nv[t];
                A2s[(qb + lk + t) * ARS + lm] = lv[t];
            }
            *reinterpret_cast<float4*>(&B1s[(qb + bk) * ARS + bn4]) = b1P;
            *reinterpret_cast<float4*>(&B2s[(qb + bk) * ARS + bn4]) = b2P;
            if (!fast) *reinterpret_cast<float4*>(&B3s[(qb + bk) * ARS + bn4]) = b3P;
            __syncthreads();
            p ^= 1;
        }
    }
    #pragma unroll
    for (int im = 0; im < 4; im++) {
        int i = m0 + (ty << 2) + im;
        if (i >= L) continue;
        int row = a * L + i;
        size_t ob = (size_t)row * STRH + n0 + (tx << 2);
        float2 na = unpack2(acn[im][0]), nb = unpack2(acn[im][1]);
        *reinterpret_cast<float4*>(&g_Sn[q][ob]) = make_float4(na.x, na.y, nb.x, nb.y);
        if (!fast) {
            float2 da = unpack2(acd[im][0]), db = unpack2(acd[im][1]);
            *reinterpret_cast<float4*>(&g_Sd[q][ob]) = make_float4(da.x, da.y, db.x, db.y);
        }
    }
}

// ============ Kernel E: col-384 GEMV + paired inverse FFT ====================
__global__ void k_E(float* __restrict__ out, const float* __restrict__ ls,
                    const float* __restrict__ noise) {
    __shared__ __align__(16) float S[4400];
    float2* fa = (float2*)S;
    float2* fb = fa + 768;
    float2* tw = fa + 1536;
    float2* red = (float2*)(S + 4224);   // 16 floats
    int b = blockIdx.x, tid = threadIdx.x;
    int r0 = 2 * b, r1 = 2 * b + 1;
    int a0 = r0 / L, i0 = r0 % L;
    int i1 = r1 % L;                      // same batch: L even -> a1 == a0
    build_tw(tw, tid);
    size_t b0 = (size_t)r0 * STRH, b1 = (size_t)r1 * STRH;
    bool fast = (g_nzero == 0);
    float rs0 = fmaxf(g_rsum[r0], 1e-7f);
    float rs1 = fmaxf(g_rsum[r1], 1e-7f);
    // ---- col 384 GEMV (k_D no longer computes it) ----
    float pn0 = 0.f, pn1 = 0.f, pd0 = 0.f, pd1 = 0.f;
    if (tid < L) {
        const float* lsb = ls    + (size_t)a0 * L * L;
        const float* nsb = noise + (size_t)a0 * L * L;
        float l0 = lsb[(size_t)i0 * L + tid], nv0 = nsb[(size_t)i0 * L + tid];
        float l1 = lsb[(size_t)i1 * L + tid], nv1 = nsb[(size_t)i1 * L + tid];
        size_t o = ((size_t)(a0 * L + tid)) * STRH + 384;
        float bb1 = g_B1[o], bb2 = g_B2[o];
        pn0 = l0 * nv0 * bb1 + l0 * bb2;
        pn1 = l1 * nv1 * bb1 + l1 * bb2;
        if (!fast) {
            float bb3 = g_B3[o];
            pd0 = l0 * bb3; pd1 = l1 * bb3;
        }
    }
    float2 n384 = blockSum256x2(make_float2(pn0, pn1), red);
    float2 d384 = blockSum256x2(make_float2(pd0, pd1), red);
    // ---- stage Y ----
    for (int c = tid; c <= 384; c += 256) {
        float n0, n1, d0, d1;
        if (c < 384) {
            n0 = 0.f; n1 = 0.f;
            #pragma unroll
            for (int s = 0; s < SPK; s++) { n0 += g_Sn[s][b0 + c]; n1 += g_Sn[s][b1 + c]; }
            if (fast) { d0 = rs0; d1 = rs1; }
            else {
                float dd0 = 0.f, dd1 = 0.f;
                #pragma unroll
                for (int s = 0; s < SPK; s++) { dd0 += g_Sd[s][b0 + c]; dd1 += g_Sd[s][b1 + c]; }
                d0 = fmaxf(dd0, 1e-7f); d1 = fmaxf(dd1, 1e-7f);
            }
        } else {
            n0 = n384.x; n1 = n384.y;
            if (fast) { d0 = rs0; d1 = rs1; }
            else { d0 = fmaxf(d384.x, 1e-7f); d1 = fmaxf(d384.y, 1e-7f); }
        }
        float sv0 = n0 / d0, sv1 = n1 / d1;
        float xr0 = g_Xr[b0 + c], xi0 = g_Xi[b0 + c];
        float m20 = xr0 * xr0 + xi0 * xi0;
        float y0r, y0i;
        if (m20 > 0.f) { float r = sv0 / sqrtf(m20); y0r = xr0 * r; y0i = xi0 * r; }
        else           { y0r = sv0; y0i = 0.f; }
        float xr1 = g_Xr[b1 + c], xi1 = g_Xi[b1 + c];
        float m21 = xr1 * xr1 + xi1 * xi1;
        float y1r, y1i;
        if (m21 > 0.f) { float r = sv1 / sqrtf(m21); y1r = xr1 * r; y1i = xi1 * r; }
        else           { y1r = sv1; y1i = 0.f; }
        fa[c] = make_float2(y0r, y0i);
        fb[c] = make_float2(y1r, y1i);
    }
    __syncthreads();
    for (int c = 385 + tid; c < 768; c += 256) {
        int m = 768 - c;
        float2 y0 = fa[m], y1 = fb[m];
        fa[c] = make_float2(y0.x + y1.y, y1.x - y0.y);
    }
    __syncthreads();
    for (int c = tid; c <= 384; c += 256) {
        float2 y0 = fa[c], y1 = fb[c];
        fa[c] = make_float2(y0.x - y1.y, y0.y + y1.x);
    }
    __syncthreads();
    float2* res = fft768r4(fa, fb, tw, tid, 1.0f);
    float* op0 = out + ((size_t)(a0 * 197 + 1 + i0)) * D;
    float* op1 = out + ((size_t)(a0 * 197 + 1 + i1)) * D;
    if (tid < 192) {
        int d = tid << 2;
        float2 v0 = res[d], v1 = res[d + 1], v2 = res[d + 2], v3 = res[d + 3];
        float4 o0 = make_float4(v0.x * (1.f / 768.f), v1.x * (1.f / 768.f),
                                v2.x * (1.f / 768.f), v3.x * (1.f / 768.f));
        float4 o1 = make_float4(v0.y * (1.f / 768.f), v1.y * (1.f / 768.f),
                                v2.y * (1.f / 768.f), v3.y * (1.f / 768.f));
        *reinterpret_cast<float4*>(op0 + d) = o0;
        *reinterpret_cast<float4*>(op1 + d) = o1;
    }
}

// ---------------- launch ------------------------------------------------------
extern "C" void kernel_launch(void* const* d_in, const int* in_sizes, int n_in,
                              void* d_out, int out_size) {
    const float* x     = (const float*)d_in[0];
    const float* imgs  = (const float*)d_in[1];
    const float* ls    = (const float*)d_in[2];
    const float* noise = (const float*)d_in[3];
    float* out = (float*)d_out;

    k_A1<<<A1_GRID, 256>>>(imgs, x, out, ls);
    k_A2<<<NLTOT / 2 + 56, 256>>>(x);
    k_C<<<NLTOT, 256>>>();
    k_D<<<dim3(6, 4, NB * SPK), 256>>>(ls, noise);
    k_E<<<NLTOT / 2, 256>>>(out, ls, noise);
}

// round 17
// speedup vs baseline: 1.0464x; 1.0464x over previous
#include <cuda_runtime.h>
#include <math.h>

#define NB 2
#define L 196
#define D 768
#define LD (L*D)
#define MW 7
#define NLTOT (NB*L)   // 392
#define STRH 448
#define SPK 7

// ---------------- scratch ---------------------------------------------------
__device__ float    g_V   [NB*LD];
__device__ float    g_Xr  [NLTOT*STRH];
__device__ float    g_Xi  [NLTOT*STRH];
__device__ float    g_sty [NLTOT*STRH];
__device__ float    g_Sn  [SPK][NLTOT*STRH];
__device__ float    g_Sd  [SPK][NLTOT*STRH];
__device__ float    g_B1  [NLTOT*STRH];
__device__ float    g_B2  [NLTOT*STRH];
__device__ float    g_B3  [NLTOT*STRH];
__device__ float    g_rsum[NLTOT];
__device__ unsigned g_M   [NB*L*MW];
__device__ int      g_nzero;

// ---------------- f32x2 helpers ---------------------------------------------
typedef unsigned long long u64;
__device__ __forceinline__ void fma2(u64 &acc, u64 a, u64 b) {
    asm("fma.rn.f32x2 %0, %1, %2, %0;" : "+l"(acc) : "l"(a), "l"(b));
}
__device__ __forceinline__ u64 pack2(float x, float y) {
    u64 r; asm("mov.b64 %0, {%1, %2};" : "=l"(r) : "f"(x), "f"(y)); return r;
}
__device__ __forceinline__ float2 unpack2(u64 v) {
    float2 f; asm("mov.b64 {%0, %1}, %2;" : "=f"(f.x), "=f"(f.y) : "l"(v)); return f;
}

__device__ __forceinline__ float2 blockSum256x2(float2 v, float2* red) {
    #pragma unroll
    for (int o = 16; o; o >>= 1) {
        v.x += __shfl_xor_sync(0xffffffffu, v.x, o);
        v.y += __shfl_xor_sync(0xffffffffu, v.y, o);
    }
    if ((threadIdx.x & 31) == 0) red[threadIdx.x >> 5] = v;
    __syncthreads();
    if (threadIdx.x < 32) {
        float2 x = (threadIdx.x < 8) ? red[threadIdx.x] : make_float2(0.f, 0.f);
        #pragma unroll
        for (int o = 4; o; o >>= 1) {
            x.x += __shfl_xor_sync(0xffffffffu, x.x, o);
            x.y += __shfl_xor_sync(0xffffffffu, x.y, o);
        }
        if (threadIdx.x == 0) red[0] = x;
    }
    __syncthreads();
    float2 r = red[0];
    __syncthreads();
    return r;
}

__device__ __forceinline__ void build_tw(float2* tw, int tid) {
    if (tid < 192) {
        float s, c; sincospif((float)tid * (1.f / 384.f), &s, &c);
        tw[tid]       = make_float2(c, s);
        tw[tid + 192] = make_float2(-s, c);
        tw[tid + 384] = make_float2(-c, -s);
    }
}

// ---------------- Stockham FFT N=768 = 3*4^4 ---------------------------------
__device__ __forceinline__ float2* fft768r4(float2* a, float2* b,
                                            const float2* tw, int tid, float sgn) {
    {
        const float c3 = 0.8660254037844386f * sgn;
        float2 x0 = a[tid], x1 = a[tid + 256], x2 = a[tid + 512];
        float2 s = make_float2(x1.x + x2.x, x1.y + x2.y);
        float2 d = make_float2(x1.x - x2.x, x1.y - x2.y);
        float mr = x0.x - 0.5f * s.x, mi = x0.y - 0.5f * s.y;
        b[3 * tid]     = make_float2(x0.x + s.x, x0.y + s.y);
        b[3 * tid + 1] = make_float2(mr - c3 * d.y, mi + c3 * d.x);
        b[3 * tid + 2] = make_float2(mr + c3 * d.y, mi - c3 * d.x);
    }
    __syncthreads();
    float2* src = b; float2* dst = a;
    #pragma unroll
    for (int st = 0; st < 4; st++) {
        const int l = 3 << (2 * st);
        const int step = 64 >> (2 * st);
        if (tid < 192) {
            int j = tid;
            int k = j % l;
            int idx = k * step;
            float2 v0 = src[j], v1 = src[j + 192], v2 = src[j + 384], v3 = src[j + 576];
            float2 w1 = tw[idx], w2 = tw[2 * idx], w3 = tw[3 * idx];
            float s1 = sgn * w1.y, s2 = sgn * w2.y, s3 = sgn * w3.y;
            float2 t1 = make_float2(v1.x * w1.x - v1.y * s1, v1.x * s1 + v1.y * w1.x);
            float2 t2 = make_float2(v2.x * w2.x - v2.y * s2, v2.x * s2 + v2.y * w2.x);
            float2 t3 = make_float2(v3.x * w3.x - v3.y * s3, v3.x * s3 + v3.y * w3.x);
            float2 e0 = make_float2(v0.x + t2.x, v0.y + t2.y);
            float2 e1 = make_float2(v0.x - t2.x, v0.y - t2.y);
            float2 o0 = make_float2(t1.x + t3.x, t1.y + t3.y);
            float2 o1 = make_float2(t1.x - t3.x, t1.y - t3.y);
            float2 io = make_float2(-sgn * o1.y, sgn * o1.x);
            int ob = 4 * j - 3 * k;
            dst[ob]         = make_float2(e0.x + o0.x, e0.y + o0.y);
            dst[ob + l]     = make_float2(e1.x + io.x, e1.y + io.y);
            dst[ob + 2 * l] = make_float2(e0.x - o0.x, e0.y - o0.y);
            dst[ob + 3 * l] = make_float2(e1.x - io.x, e1.y - io.y);
        }
        __syncthreads();
        float2* t = src; src = dst; dst = t;
    }
    return src;
}

// ============ Kernel A1: paired patch(196) | rowsum(49) | misc(11) ===========
#define A1_PATCH 196
#define A1_RS    49
#define A1_MISC  11
#define A1_GRID  (A1_PATCH + A1_RS + A1_MISC)

__global__ void k_A1(const float* __restrict__ imgs, const float* __restrict__ x,
                     float* __restrict__ out, const float* __restrict__ ls) {
    __shared__ float2 red[8];
    __shared__ float buf[2 * D];
    int b = blockIdx.x, tid = threadIdx.x;
    if (b < A1_PATCH) {
        int p = tid >> 4, q = tid & 15;
        const float* base[2];
        #pragma unroll
        for (int rr = 0; rr < 2; rr++) {
            int blk = 2 * b + rr, a = blk / L, l = blk % L;
            int hh = l / 14, ww = l % 14;
            base[rr] = imgs + ((size_t)a * 3 * 224 + (size_t)(hh * 16 + p)) * 224
                            + (ww * 16 + q);
        }
        float v0[3], v1[3];
        #pragma unroll
        for (int c = 0; c < 3; c++) {
            v0[c] = base[0][(size_t)c * 224 * 224];
            v1[c] = base[1][(size_t)c * 224 * 224];
        }
        float2 sums = blockSum256x2(
            make_float2(v0[0] + v0[1] + v0[2], v1[0] + v1[1] + v1[2]), red);
        float mean0 = sums.x * (1.f / 768.f), mean1 = sums.y * (1.f / 768.f);
        float u0[3], u1[3]; float ss0 = 0.f, ss1 = 0.f;
        #pragma unroll
        for (int c = 0; c < 3; c++) {
            u0[c] = v0[c] - mean0; ss0 += u0[c] * u0[c];
            u1[c] = v1[c] - mean1; ss1 += u1[c] * u1[c];
        }
        float2 tot = blockSum256x2(make_float2(ss0, ss1), red);
        float inv0 = 1.f / sqrtf(tot.x);
        float inv1 = 1.f / sqrtf(tot.y);
        #pragma unroll
        for (int c = 0; c < 3; c++) {
            buf[tid * 3 + c]     = u0[c] * inv0;
            buf[D + tid * 3 + c] = u1[c] * inv1;
        }
        __syncthreads();
        if (tid < 192) {
            reinterpret_cast<float4*>(g_V + (size_t)(2 * b) * D)[tid] =
                reinterpret_cast<float4*>(buf)[tid];
            reinterpret_cast<float4*>(g_V + (size_t)(2 * b + 1) * D)[tid] =
                reinterpret_cast<float4*>(buf + D)[tid];
        }
        return;
    }
    b -= A1_PATCH;
    if (b < A1_RS) {
        int w = tid >> 5, lane = tid & 31;
        int row = b * 8 + w;
        if (row < NLTOT) {
            int a = row / L, i = row % L;
            const float* lp = ls + ((size_t)a * L + i) * L;
            float s = 0.f;
            for (int j = lane; j < L; j += 32) s += lp[j];
            #pragma unroll
            for (int o = 16; o; o >>= 1) s += __shfl_xor_sync(0xffffffffu, s, o);
            if (lane == 0) g_rsum[row] = s;
        }
        return;
    }
    b -= A1_RS;
    {
        int t = b * 256 + tid;
        if (t < NB * L * MW) g_M[t] = 0u;
        if (t < NB * D) {
            int a = t / D, d = t % D;
            out[(size_t)a * 197 * D + d] = x[(size_t)a * 197 * D + d];
        }
        if (t == 0) g_nzero = 0;
    }
}

// ============ Kernel A2: paired fwd FFT(196) | sim(56) — one wave ============
__global__ void k_A2(const float* __restrict__ x) {
    __shared__ __align__(16) float S[4400];
    int b = blockIdx.x, tid = threadIdx.x;
    if (b < NLTOT / 2) {
        float2* fa = (float2*)S;
        float2* fb = fa + 768;
        float2* tw = fa + 1536;
        build_tw(tw, tid);
        int r0 = 2 * b, r1 = 2 * b + 1;
        int a0 = r0 / L, i0 = r0 % L;
        int a1 = r1 / L, i1 = r1 % L;
        const float* xp0 = x + ((size_t)(a0 * 197 + 1 + i0)) * D;
        const float* xp1 = x + ((size_t)(a1 * 197 + 1 + i1)) * D;
        for (int d = tid; d < D; d += 256)
            fa[d] = make_float2(xp0[d], xp1[d]);
        __syncthreads();
        float2* res = fft768r4(fa, fb, tw, tid, -1.0f);
        size_t b0 = (size_t)r0 * STRH, b1 = (size_t)r1 * STRH;
        for (int k = tid; k <= 384; k += 256) {
            float2 Zk = res[k];
            float2 Zn = res[(768 - k) % 768];
            float x0r = 0.5f * (Zk.x + Zn.x), x0i = 0.5f * (Zk.y - Zn.y);
            float x1r = 0.5f * (Zk.y + Zn.y), x1i = 0.5f * (Zn.x - Zk.x);
            g_Xr[b0 + k] = x0r; g_Xi[b0 + k] = x0i;
            g_sty[b0 + k] = sqrtf(x0r * x0r + x0i * x0i);
            g_Xr[b1 + k] = x1r; g_Xi[b1 + k] = x1i;
            g_sty[b1 + k] = sqrtf(x1r * x1r + x1i * x1i);
        }
        return;
    }
    {
        // ---- sim: 32x32 upper-tri tile, double-buffered ----
        int bb = b - NLTOT / 2;
        int a = bb / 28;
        int t = bb % 28, bi = 0;
        while (t >= 7 - bi) { t -= 7 - bi; bi++; }
        int bj = bi + t;
        int i0 = bi * 32, j0 = bj * 32;
        float (*As)[34] = (float(*)[34])S;
        float (*Bs)[34] = (float(*)[34])(S + 2176);
        int tx = tid & 15, ty = tid >> 4;
        int m = tid >> 3, k4 = (tid & 7) << 2;
        const float* Vb = g_V + (size_t)a * LD;
        const float* Arow = (i0 + m < L) ? Vb + (size_t)(i0 + m) * D : nullptr;
        const float* Brow = (j0 + m < L) ? Vb + (size_t)(j0 + m) * D : nullptr;
        float4 z4 = make_float4(0.f, 0.f, 0.f, 0.f);
        float4 avP = Arow ? *reinterpret_cast<const float4*>(Arow + k4) : z4;
        float4 bvP = Brow ? *reinterpret_cast<const float4*>(Brow + k4) : z4;
        u64 acc[2] = {0ULL, 0ULL};
        int p = 0;
        As[k4 + 0][m] = avP.x; As[k4 + 1][m] = avP.y;
        As[k4 + 2][m] = avP.z; As[k4 + 3][m] = avP.w;
        Bs[k4 + 0][m] = bvP.x; Bs[k4 + 1][m] = bvP.y;
        Bs[k4 + 2][m] = bvP.z; Bs[k4 + 3][m] = bvP.w;
        __syncthreads();
        for (int k0 = 0; k0 < D; k0 += 32) {
            int kn = k0 + 32;
            if (kn < D) {
                avP = Arow ? *reinterpret_cast<const float4*>(Arow + kn + k4) : z4;
                bvP = Brow ? *reinterpret_cast<const float4*>(Brow + kn + k4) : z4;
            }
            int pb = p * 32;
            #pragma unroll
            for (int kk = 0; kk < 32; kk++) {
                float2 a2 = *reinterpret_cast<float2*>(&As[pb + kk][ty << 1]);
                u64 bbv = *reinterpret_cast<u64*>(&Bs[pb + kk][tx << 1]);
                fma2(acc[0], pack2(a2.x, a2.x), bbv);
                fma2(acc[1], pack2(a2.y, a2.y), bbv);
            }
            if (kn < D) {
                int qb = (1 - p) * 32;
                As[qb + k4 + 0][m] = avP.x; As[qb + k4 + 1][m] = avP.y;
                As[qb + k4 + 2][m] = avP.z; As[qb + k4 + 3][m] = avP.w;
                Bs[qb + k4 + 0][m] = bvP.x; Bs[qb + k4 + 1][m] = bvP.y;
                Bs[qb + k4 + 2][m] = bvP.z; Bs[qb + k4 + 3][m] = bvP.w;
                __syncthreads();
                p ^= 1;
            }
        }
        #pragma unroll
        for (int r = 0; r < 2; r++) {
            int i = i0 + (ty << 1) + r;
            if (i >= L) continue;
            float2 c = unpack2(acc[r]);
            int j = j0 + (tx << 1);
            if (j < L && j >= i && c.x > 0.3f)
                atomicOr(&g_M[(a * L + i) * MW + (j >> 5)], 1u << (j & 31));
            j++;
            if (j < L && j >= i && c.y > 0.3f)
                atomicOr(&g_M[(a * L + i) * MW + (j >> 5)], 1u << (j & 31));
        }
    }
}

// ============ Kernel C: per-row prop replay + stats + nzero ==================
__global__ void k_C() {
    __shared__ unsigned m[NB * L * MW];
    __shared__ int sS, sRem, ired[8];
    int blk = blockIdx.x, a = blk / L, i = blk % L;
    int tid = threadIdx.x;
    int local = 0;
    for (int t = tid; t < NB * L * MW; t += 256) {
        unsigned w = g_M[t]; m[t] = w; local += __popc(w);
    }
    #pragma unroll
    for (int o = 16; o; o >>= 1) local += __shfl_xor_sync(0xffffffffu, local, o);
    if ((tid & 31) == 0) ired[tid >> 5] = local;
    __syncthreads();
    if (tid == 0) {
        int s = 0;
        #pragma unroll
        for (int w = 0; w < 8; w++) s += ired[w];
        sS = s;
    }
    __syncthreads();
    for (int ii = 0; ii < i; ii++) {
        if (sS == NB * L) break;
        if (tid == 0) sRem = 0;
        __syncthreads();
        int rem = 0;
        int nj = L - 1 - ii;
        int cnt = NB * nj * MW;
        for (int t = tid; t < cnt; t += 256) {
            int w = t % MW; int r = t / MW;
            int j = ii + 1 + (r % nj); int aa = r / nj;
            unsigned rw  = m[(aa * L + ii) * MW + w];
            unsigned old = m[(aa * L + j) * MW + w];
            unsigned drop = old & rw;
            if (drop) { m[(aa * L + j) * MW + w] = old & ~rw; rem += __popc(drop); }
        }
        #pragma unroll
        for (int o = 16; o; o >>= 1) rem += __shfl_xor_sync(0xffffffffu, rem, o);
        if ((tid & 31) == 0 && rem) atomicAdd(&sRem, rem);
        __syncthreads();
        if (tid == 0) sS -= sRem;
        __syncthreads();
    }
    const unsigned* mw = &m[(a * L + i) * MW];
    int num = 0;
    #pragma unroll
    for (int w = 0; w < MW; w++) num += __popc(mw[w]);
    float numc = (num > 0) ? (float)num : 1e-7f;
    bool has2 = tid < 129;
    int c1 = tid, c2 = tid + 256;
    float S1a = 0.f, S1b = 0.f;
    for (int w = 0; w < MW; w++) {
        unsigned bits = mw[w];
        while (bits) {
            int j = (w << 5) + __ffs((int)bits) - 1; bits &= bits - 1;
            const float* sp = g_sty + (size_t)(a * L + j) * STRH;
            S1a += sp[c1];
            if (has2) S1b += sp[c2];
        }
    }
    float avga = S1a / numc, avgb = S1b / numc;
    float S2a = 0.f, S2b = 0.f;
    for (int w = 0; w < MW; w++) {
        unsigned bits = mw[w];
        while (bits) {
            int j = (w << 5) + __ffs((int)bits) - 1; bits &= bits - 1;
            const float* sp = g_sty + (size_t)(a * L + j) * STRH;
            float xa = sp[c1] - avga; S2a += xa * xa;
            if (has2) { float xb = sp[c2] - avgb; S2b += xb * xb; }
        }
    }
    size_t off = (size_t)blk * STRH;
    float sta = sqrtf(S2a / numc);
    float ma = (S1a > 0.f) ? 1.f : 0.f;
    if (!(S1a > 0.f)) atomicAdd(&g_nzero, 1);
    g_B1[off + c1] = ma * sta; g_B2[off + c1] = ma * avga; g_B3[off + c1] = ma;
    if (has2) {
        float stb = sqrtf(S2b / numc);
        float mb = (S1b > 0.f) ? 1.f : 0.f;
        if (!(S1b > 0.f)) atomicAdd(&g_nzero, 1);
        g_B1[off + c2] = mb * stb; g_B2[off + c2] = mb * avgb; g_B3[off + c2] = mb;
    } else if (tid < 192) {
        g_B1[off + c2] = 0.f; g_B2[off + c2] = 0.f; g_B3[off + c2] = 0.f;
    }
}

// ============ Kernel D: split-K(7) GEMM + dead-warp row skip =================
#define ARS 68
__global__ void __launch_bounds__(256, 3)
k_D(const float* __restrict__ ls, const float* __restrict__ noise) {
    __shared__ __align__(16) float SD[5 * 32 * ARS];
    __shared__ int s_nz;
    float* A1s = SD;
    float* A2s = SD + 32 * ARS;
    float* B1s = SD + 64 * ARS;
    float* B2s = SD + 96 * ARS;
    float* B3s = SD + 128 * ARS;
    int tid = threadIdx.x;
    if (tid == 0) s_nz = g_nzero;
    int tx = tid & 15, ty = tid >> 4;
    int n0 = blockIdx.x * 64, m0 = blockIdx.y * 64;
    int a = blockIdx.z / SPK, q = blockIdx.z % SPK;
    int kbeg = (q == 0) ? 0 : 16 + 32 * (q - 1);
    int kend = 16 + 32 * q;
    bool rowAct = (m0 + (ty << 2)) < L;     // warp-uniform: skip dead rows
    u64 acn[4][2], acd[4][2];
    #pragma unroll
    for (int i = 0; i < 4; i++) {
        acn[i][0] = acn[i][1] = 0ULL;
        acd[i][0] = acd[i][1] = 0ULL;
    }
    int lm = tid >> 2, lk = (tid & 3) << 2;
    int bk = tid >> 4, bn4 = (tid & 15) << 2;
    const float* lsb = ls    + (size_t)a * L * L;
    const float* nsb = noise + (size_t)a * L * L;
    float4 z4 = make_float4(0.f, 0.f, 0.f, 0.f);
    int ia = m0 + lm;
    bool iav = ia < L;
    float4 lvP = z4, nvP = z4;
    {
        int ja = kbeg + lk;
        if (iav && ja < L) {
            lvP = *reinterpret_cast<const float4*>(lsb + (size_t)ia * L + ja);
            nvP = *reinterpret_cast<const float4*>(nsb + (size_t)ia * L + ja);
        }
    }
    float4 b1P = z4, b2P = z4, b3P = z4;
    __syncthreads();
    bool fast = (s_nz == 0);
    {
        int jb = kbeg + bk;
        if (jb < L) {
            size_t o = (size_t)(a * L + jb) * STRH + n0 + bn4;
            b1P = *reinterpret_cast<const float4*>(&g_B1[o]);
            b2P = *reinterpret_cast<const float4*>(&g_B2[o]);
            if (!fast) b3P = *reinterpret_cast<const float4*>(&g_B3[o]);
        }
    }
    int p = 0;
    {
        const float* lv = reinterpret_cast<const float*>(&lvP);
        const float* nv = reinterpret_cast<const float*>(&nvP);
        #pragma unroll
        for (int t = 0; t < 4; t++) {
            A1s[(lk + t) * ARS + lm] = lv[t] * nv[t];
            A2s[(lk + t) * ARS + lm] = lv[t];
        }
        *reinterpret_cast<float4*>(&B1s[bk * ARS + bn4]) = b1P;
        *reinterpret_cast<float4*>(&B2s[bk * ARS + bn4]) = b2P;
        if (!fast) *reinterpret_cast<float4*>(&B3s[bk * ARS + bn4]) = b3P;
    }
    __syncthreads();
    for (int k0 = kbeg; k0 < kend; k0 += 16) {
        int kn = k0 + 16;
        if (kn < kend) {
            lvP = z4; nvP = z4;
            int ja = kn + lk;
            if (iav && ja < L) {
                lvP = *reinterpret_cast<const float4*>(lsb + (size_t)ia * L + ja);
                nvP = *reinterpret_cast<const float4*>(nsb + (size_t)ia * L + ja);
            }
            int jb = kn + bk;
            b1P = z4; b2P = z4; b3P = z4;
            if (jb < L) {
                size_t o = (size_t)(a * L + jb) * STRH + n0 + bn4;
                b1P = *reinterpret_cast<const float4*>(&g_B1[o]);
                b2P = *reinterpret_cast<const float4*>(&g_B2[o]);
                if (!fast) b3P = *reinterpret_cast<const float4*>(&g_B3[o]);
            }
        }
        int pb = p * 16;
        if (rowAct) {
            if (fast) {
                #pragma unroll
                for (int kk = 0; kk < 16; kk++) {
                    float4 a1 = *reinterpret_cast<float4*>(&A1s[(pb + kk) * ARS + (ty << 2)]);
                    float4 a2 = *reinterpret_cast<float4*>(&A2s[(pb + kk) * ARS + (ty << 2)]);
                    ulonglong2 b1 = *reinterpret_cast<ulonglong2*>(&B1s[(pb + kk) * ARS + (tx << 2)]);
                    ulonglong2 b2 = *reinterpret_cast<ulonglong2*>(&B2s[(pb + kk) * ARS + (tx << 2)]);
                    u64 aa;
                    aa = pack2(a1.x, a1.x); fma2(acn[0][0], aa, b1.x); fma2(acn[0][1], aa, b1.y);
                    aa = pack2(a2.x, a2.x); fma2(acn[0][0], aa, b2.x); fma2(acn[0][1], aa, b2.y);
                    aa = pack2(a1.y, a1.y); fma2(acn[1][0], aa, b1.x); fma2(acn[1][1], aa, b1.y);
                    aa = pack2(a2.y, a2.y); fma2(acn[1][0], aa, b2.x); fma2(acn[1][1], aa, b2.y);
                    aa = pack2(a1.z, a1.z); fma2(acn[2][0], aa, b1.x); fma2(acn[2][1], aa, b1.y);
                    aa = pack2(a2.z, a2.z); fma2(acn[2][0], aa, b2.x); fma2(acn[2][1], aa, b2.y);
                    aa = pack2(a1.w, a1.w); fma2(acn[3][0], aa, b1.x); fma2(acn[3][1], aa, b1.y);
                    aa = pack2(a2.w, a2.w); fma2(acn[3][0], aa, b2.x); fma2(acn[3][1], aa, b2.y);
                }
            } else {
                #pragma unroll
                for (int kk = 0; kk < 16; kk++) {
                    float4 a1 = *reinterpret_cast<float4*>(&A1s[(pb + kk) * ARS + (ty << 2)]);
                    float4 a2 = *reinterpret_cast<float4*>(&A2s[(pb + kk) * ARS + (ty << 2)]);
                    ulonglong2 b1 = *reinterpret_cast<ulonglong2*>(&B1s[(pb + kk) * ARS + (tx << 2)]);
                    ulonglong2 b2 = *reinterpret_cast<ulonglong2*>(&B2s[(pb + kk) * ARS + (tx << 2)]);
                    ulonglong2 b3 = *reinterpret_cast<ulonglong2*>(&B3s[(pb + kk) * ARS + (tx << 2)]);
                    u64 aa;
                    aa = pack2(a1.x, a1.x); fma2(acn[0][0], aa, b1.x); fma2(acn[0][1], aa, b1.y);
                    aa = pack2(a2.x, a2.x); fma2(acn[0][0], aa, b2.x); fma2(acn[0][1], aa, b2.y);
                                            fma2(acd[0][0], aa, b3.x); fma2(acd[0][1], aa, b3.y);
                    aa = pack2(a1.y, a1.y); fma2(acn[1][0], aa, b1.x); fma2(acn[1][1], aa, b1.y);
                    aa = pack2(a2.y, a2.y); fma2(acn[1][0], aa, b2.x); fma2(acn[1][1], aa, b2.y);
                                            fma2(acd[1][0], aa, b3.x); fma2(acd[1][1], aa, b3.y);
                    aa = pack2(a1.z, a1.z); fma2(acn[2][0], aa, b1.x); fma2(acn[2][1], aa, b1.y);
                    aa = pack2(a2.z, a2.z); fma2(acn[2][0], aa, b2.x); fma2(acn[2][1], aa, b2.y);
                                            fma2(acd[2][0], aa, b3.x); fma2(acd[2][1], aa, b3.y);
                    aa = pack2(a1.w, a1.w); fma2(acn[3][0], aa, b1.x); fma2(acn[3][1], aa, b1.y);
                    aa = pack2(a2.w, a2.w); fma2(acn[3][0], aa, b2.x); fma2(acn[3][1], aa, b2.y);
                                            fma2(acd[3][0], aa, b3.x); fma2(acd[3][1], aa, b3.y);
                }
            }
        }
        if (kn < kend) {
            int qb = (1 - p) * 16;
            const float* lv = reinterpret_cast<const float*>(&lvP);
            const float* nv = reinterpret_cast<const float*>(&nvP);
            #pragma unroll
            for (int t = 0; t < 4; t++) {
                A1s[(qb + lk + t) * ARS + lm] = lv[t] * nv[t];
                A2s[(qb + lk + t) * ARS + lm] = lv[t];
            }
            *reinterpret_cast<float4*>(&B1s[(qb + bk) * ARS + bn4]) = b1P;
            *reinterpret_cast<float4*>(&B2s[(qb + bk) * ARS + bn4]) = b2P;
            if (!fast) *reinterpret_cast<float4*>(&B3s[(qb + bk) * ARS + bn4]) = b3P;
            __syncthreads();
            p ^= 1;
        }
    }
    #pragma unroll
    for (int im = 0; im < 4; im++) {
        int i = m0 + (ty << 2) + im;
        if (i >= L) continue;
        int row = a * L + i;
        size_t ob = (size_t)row * STRH + n0 + (tx << 2);
        float2 na = unpack2(acn[im][0]), nb = unpack2(acn[im][1]);
        *reinterpret_cast<float4*>(&g_Sn[q][ob]) = make_float4(na.x, na.y, nb.x, nb.y);
        if (!fast) {
            float2 da = unpack2(acd[im][0]), db = unpack2(acd[im][1]);
            *reinterpret_cast<float4*>(&g_Sd[q][ob]) = make_float4(da.x, da.y, db.x, db.y);
        }
    }
}

// ============ Kernel E: paired inverse FFT (2 rows per block) ================
__global__ void k_E(float* __restrict__ out) {
    __shared__ __align__(16) float S[4400];
    float2* fa = (float2*)S;
    float2* fb = fa + 768;
    float2* tw = fa + 1536;
    int b = blockIdx.x, tid = threadIdx.x;
    int r0 = 2 * b, r1 = 2 * b + 1;
    int a0 = r0 / L, i0 = r0 % L;
    int a1 = r1 / L, i1 = r1 % L;
    build_tw(tw, tid);
    size_t b0 = (size_t)r0 * STRH, b1 = (size_t)r1 * STRH;
    bool fast = (g_nzero == 0);
    float rs0 = fmaxf(g_rsum[r0], 1e-7f);
    float rs1 = fmaxf(g_rsum[r1], 1e-7f);
    for (int c = tid; c <= 384; c += 256) {
        float n0 = 0.f, n1 = 0.f;
        #pragma unroll
        for (int s = 0; s < SPK; s++) { n0 += g_Sn[s][b0 + c]; n1 += g_Sn[s][b1 + c]; }
        float d0, d1;
        if (fast) { d0 = rs0; d1 = rs1; }
        else {
            float dd0 = 0.f, dd1 = 0.f;
            #pragma unroll
            for (int s = 0; s < SPK; s++) { dd0 += g_Sd[s][b0 + c]; dd1 += g_Sd[s][b1 + c]; }
            d0 = fmaxf(dd0, 1e-7f); d1 = fmaxf(dd1, 1e-7f);
        }
        float sv0 = n0 / d0, sv1 = n1 / d1;
        float xr0 = g_Xr[b0 + c], xi0 = g_Xi[b0 + c];
        float m20 = xr0 * xr0 + xi0 * xi0;
        float y0r, y0i;
        if (m20 > 0.f) { float r = sv0 / sqrtf(m20); y0r = xr0 * r; y0i = xi0 * r; }
        else           { y0r = sv0; y0i = 0.f; }
        float xr1 = g_Xr[b1 + c], xi1 = g_Xi[b1 + c];
        float m21 = xr1 * xr1 + xi1 * xi1;
        float y1r, y1i;
        if (m21 > 0.f) { float r = sv1 / sqrtf(m21); y1r = xr1 * r; y1i = xi1 * r; }
        else           { y1r = sv1; y1i = 0.f; }
        fa[c] = make_float2(y0r, y0i);
        fb[c] = make_float2(y1r, y1i);
    }
    __syncthreads();
    for (int c = 385 + tid; c < 768; c += 256) {
        int m = 768 - c;
        float2 y0 = fa[m], y1 = fb[m];
        fa[c] = make_float2(y0.x + y1.y, y1.x - y0.y);
    }
    __syncthreads();
    for (int c = tid; c <= 384; c += 256) {
        float2 y0 = fa[c], y1 = fb[c];
        fa[c] = make_float2(y0.x - y1.y, y0.y + y1.x);
    }
    __syncthreads();
    float2* res = fft768r4(fa, fb, tw, tid, 1.0f);
    float* op0 = out + ((size_t)(a0 * 197 + 1 + i0)) * D;
    float* op1 = out + ((size_t)(a1 * 197 + 1 + i1)) * D;
    if (tid < 192) {
        int d = tid << 2;
        float2 v0 = res[d], v1 = res[d + 1], v2 = res[d + 2], v3 = res[d + 3];
        float4 o0 = make_float4(v0.x * (1.f / 768.f), v1.x * (1.f / 768.f),
                                v2.x * (1.f / 768.f), v3.x * (1.f / 768.f));
        float4 o1 = make_float4(v0.y * (1.f / 768.f), v1.y * (1.f / 768.f),
                                v2.y * (1.f / 768.f), v3.y * (1.f / 768.f));
        *reinterpret_cast<float4*>(op0 + d) = o0;
        *reinterpret_cast<float4*>(op1 + d) = o1;
    }
}

// ---------------- launch ------------------------------------------------------
extern "C" void kernel_launch(void* const* d_in, const int* in_sizes, int n_in,
                              void* d_out, int out_size) {
    const float* x     = (const float*)d_in[0];
    const float* imgs  = (const float*)d_in[1];
    const float* ls    = (const float*)d_in[2];
    const float* noise = (const float*)d_in[3];
    float* out = (float*)d_out;

    k_A1<<<A1_GRID, 256>>>(imgs, x, out, ls);
    k_A2<<<NLTOT / 2 + 56, 256>>>(x);
    k_C<<<NLTOT, 256>>>();
    k_D<<<dim3(7, 4, NB * SPK), 256>>>(ls, noise);
    k_E<<<NLTOT / 2, 256>>>(out);
}